// round 16
// baseline (speedup 1.0000x reference)
#include <cuda_runtime.h>
#include <cuda_fp16.h>
#include <cstdint>

// ---------------- problem constants ----------------
#define TT 50176
#define DD 1024
#define EE 2048
#define NS 8
#define EPS 1e-5f

#define NBLK 392
#define NET 16
#define NKC 32
#define CHU 2048
#define STG 3
#define STAGE_U32 8192
#define SU_BYTE   (STG * STAGE_U32 * 4)
#define MBAR_BYTE (SU_BYTE + 4096)
#define BCAST_BYTE (MBAR_BYTE + 48)
#define SMEM_BYTES (BCAST_BYTE + 16)

// unit space: [0,17) W-pack(16)+Wst(1); [17,409) x-pack; [409,3545) GEMM
#define NU_W 17
#define NU_PREP (NU_W + NBLK)
#define NU_TOT (NU_PREP + NBLK * 8)
#define GRID_P 304

// ---------------- scratch ----------------
__device__ uint32_t g_xnt[(size_t)NBLK * NKC * CHU];
__device__ uint32_t g_wpt[(size_t)NET * NKC * CHU];
__device__ float    g_wst[EE * NS];
__device__ float    g_su[(size_t)NBLK * 1024];
__device__ int      g_unit;
__device__ int      g_done[NBLK];
__device__ int      g_xready[NBLK];
__device__ int      g_wdone;

// ---------------- helpers ----------------
__device__ __forceinline__ float silu_f(float v) { return v * (1.0f / (1.0f + __expf(-v))); }
__device__ __forceinline__ uint32_t smem_u32(const void* p) {
    uint32_t a;
    asm("{ .reg .u64 t; cvta.to.shared.u64 t, %1; cvt.u32.u64 %0, t; }" : "=r"(a) : "l"(p));
    return a;
}
__device__ __forceinline__ uint32_t pack_h2(float lo, float hi) {
    __half2 h = __halves2half2(__float2half_rn(lo), __float2half_rn(hi));
    return *reinterpret_cast<uint32_t*>(&h);
}
#define CP_ASYNC16(dst, src) \
    asm volatile("cp.async.cg.shared.global [%0], [%1], 16;" :: "r"(dst), "l"(src))
#define CPA_MBAR_ARRIVE(addr) \
    asm volatile("cp.async.mbarrier.arrive.noinc.shared.b64 [%0];" :: "r"(addr) : "memory")
#define MBARRIER_INIT(addr, cnt) \
    asm volatile("mbarrier.init.shared.b64 [%0], %1;" :: "r"(addr), "r"(cnt) : "memory")
#define MBAR_ARRIVE(addr) \
    asm volatile("mbarrier.arrive.shared.b64 _, [%0];" :: "r"(addr) : "memory")

#define MBARRIER_WAIT(addr, ph) do {                                            \
    uint32_t _m = (addr), _p = (uint32_t)(ph), _d;                              \
    asm volatile("{ .reg .pred p; mbarrier.try_wait.parity.acquire.cta.shared::cta.b64 p, [%1], %2; selp.b32 %0,1,0,p; }" \
        : "=r"(_d) : "r"(_m), "r"(_p) : "memory");                              \
    if (!_d) { asm volatile(                                                    \
        "{ .reg .pred P; WL%=: mbarrier.try_wait.parity.acquire.cta.shared::cta.b64 P, [%0], %1, 0x989680;" \
        " @P bra.uni WD%=; bra.uni WL%=; WD%=: }" :: "r"(_m), "r"(_p) : "memory"); } \
} while (0)

#define MBARRIER_WAIT_RELAXED(addr, ph) do {                                    \
    uint32_t _m = (addr), _p = (uint32_t)(ph), _d;                              \
    asm volatile("{ .reg .pred p; mbarrier.try_wait.parity.relaxed.cta.shared::cta.b64 p, [%1], %2, 0x989680; selp.b32 %0,1,0,p; }" \
        : "=r"(_d) : "r"(_m), "r"(_p) : "memory");                              \
    if (!_d) { asm volatile(                                                    \
        "{ .reg .pred P; WL%=: mbarrier.try_wait.parity.relaxed.cta.shared::cta.b64 P, [%0], %1, 0x989680;" \
        " @P bra.uni WD%=; bra.uni WL%=; WD%=: }" :: "r"(_m), "r"(_p) : "memory"); } \
} while (0)

__device__ __forceinline__ void mma_f16(float d[4], const uint32_t a[4],
                                        uint32_t b0, uint32_t b1) {
    asm volatile(
        "mma.sync.aligned.m16n8k16.row.col.f32.f16.f16.f32 "
        "{%0,%1,%2,%3}, {%4,%5,%6,%7}, {%8,%9}, {%0,%1,%2,%3};"
        : "+f"(d[0]), "+f"(d[1]), "+f"(d[2]), "+f"(d[3])
        : "r"(a[0]), "r"(a[1]), "r"(a[2]), "r"(a[3]), "r"(b0), "r"(b1));
}

// ---------------- kernel 0: zero scratch + counters ----------------
__global__ void __launch_bounds__(1024)
zerok() {
    const int b = blockIdx.x, tid = threadIdx.x;
    g_su[(size_t)b * 1024 + tid] = 0.f;
    if (tid == 0) {
        g_done[b] = 0;
        g_xready[b] = 0;
        if (b == 0) { g_unit = 0; g_wdone = 0; }
    }
}

// ---- persistent kernel: prep units + GEMM units, one dynamic queue ----
__global__ void __launch_bounds__(256, 2)
mamba_pers(const float* __restrict__ x,   const float* __restrict__ Wp,
           const float* __restrict__ gamma, const float* __restrict__ beta,
           const float* __restrict__ Wst, const float* __restrict__ bp,
           const float* __restrict__ bst, const float* __restrict__ Wo,
           const float* __restrict__ bo,  const float* __restrict__ istate,
           float* __restrict__ out)
{
    extern __shared__ uint32_t smu[];
    float* s_su = reinterpret_cast<float*>(reinterpret_cast<char*>(smu) + SU_BYTE);
    int*  s_bc  = reinterpret_cast<int*>(reinterpret_cast<char*>(smu) + BCAST_BYTE);
    float* s_t    = reinterpret_cast<float*>(smu);          // prep scratch
    float* s_mu   = s_t + 128 * 36;
    float* s_rstd = s_mu + 128;
    const int tid = threadIdx.x, lane = tid & 31, wid = tid >> 5;
    const int wm = wid >> 2, wn = wid & 3;
    const uint32_t sb = smem_u32(smu);
    const uint32_t mb_full = sb + MBAR_BYTE;
    const uint32_t mb_free = sb + MBAR_BYTE + 24;
    const int g = lane >> 2, t = lane & 3;

    if (tid == 0) {
#pragma unroll
        for (int s = 0; s < STG; s++) {
            MBARRIER_INIT(mb_full + 8 * s, 256);   // cp.async completion arrives
            MBARRIER_INIT(mb_free + 8 * s, 8);     // warp-level consume arrives
        }
    }
    __syncthreads();

    const int aoff = wm * 1024 + lane * 4;
    const int boff = 4096 + wn * 512 + lane * 4;

    uint32_t rc = 0;
    bool wok = false;

    for (;;) {
        __syncthreads();
        if (tid == 0) s_bc[0] = atomicAdd(&g_unit, 1);
        __syncthreads();
        const int u = s_bc[0];
        if (u >= NU_TOT) break;

        if (u < NU_PREP) {
            // ================= PREP UNIT =================
            if (u == NU_W - 1) {          // Wst transpose
                for (int i = tid; i < EE * NS; i += 256) {
                    int e = i >> 3, n = i & 7;
                    g_wst[i] = Wst[n * EE + e];
                }
                __threadfence();
                __syncthreads();
                if (tid == 0) atomicAdd(&g_wdone, 1);
                continue;
            }
            const bool isW = (u < NU_W - 1);
            const int pb = isW ? u : (u - NU_W);
            const float* src = isW ? Wp + (size_t)pb * 128 * DD
                                   : x + (size_t)pb * 128 * DD;
            uint32_t* dst = isW ? g_wpt + (size_t)pb * NKC * CHU
                                : g_xnt + (size_t)pb * NKC * CHU;

            if (!isW) {
                int tk = tid >> 1, half = tid & 1;
                const float4* xr = reinterpret_cast<const float4*>(
                    src + (size_t)tk * DD + half * (DD / 2));
                float s = 0.f, ss = 0.f;
#pragma unroll 4
                for (int i = 0; i < DD / 8; i++) {
                    float4 v = xr[i];
                    s  += v.x + v.y + v.z + v.w;
                    ss += v.x * v.x + v.y * v.y + v.z * v.z + v.w * v.w;
                }
                s  += __shfl_xor_sync(0xFFFFFFFFu, s, 1);
                ss += __shfl_xor_sync(0xFFFFFFFFu, ss, 1);
                if (!half) {
                    float mu = s * (1.0f / DD);
                    float var = ss * (1.0f / DD) - mu * mu;
                    s_mu[tk] = mu; s_rstd[tk] = rsqrtf(var + EPS);
                }
            }
            __syncthreads();

            for (int kc = 0; kc < NKC; kc++) {
#pragma unroll
                for (int i = 0; i < 4; i++) {
                    int id = i * 256 + tid;
                    int row = id >> 3, c4 = id & 7;
                    float4 v = *reinterpret_cast<const float4*>(
                        src + (size_t)row * DD + kc * 32 + c4 * 4);
                    *reinterpret_cast<float4*>(s_t + row * 36 + c4 * 4) = v;
                }
                __syncthreads();
                if (isW) {
#pragma unroll
                    for (int j = 0; j < 8; j++) {
                        int o = j * 256 + tid;
                        int MS = o >> 7, NFP = MS >> 1, ks = MS & 1;
                        int ln = (o >> 2) & 31, gg = ln >> 2, tt = ln & 3, jj = o & 3;
                        int n  = NFP * 16 + (jj >> 1) * 8 + gg;
                        int k0 = ks * 16 + (jj & 1) * 8 + 2 * tt;
                        dst[(size_t)kc * CHU + o] =
                            pack_h2(s_t[n * 36 + k0], s_t[n * 36 + k0 + 1]);
                    }
                } else {
#pragma unroll
                    for (int j = 0; j < 8; j++) {
                        int o = j * 256 + tid;
                        int MS = o >> 7, MF = MS >> 1, ks = MS & 1;
                        int ln = (o >> 2) & 31, gg = ln >> 2, tt = ln & 3, r = o & 3;
                        int m  = MF * 16 + (r & 1) * 8 + gg;
                        int k0 = ks * 16 + (r >> 1) * 8 + 2 * tt;
                        int kg = kc * 32 + k0;
                        float v0 = fmaf((s_t[m * 36 + k0]     - s_mu[m]) * s_rstd[m],
                                        gamma[kg], beta[kg]);
                        float v1 = fmaf((s_t[m * 36 + k0 + 1] - s_mu[m]) * s_rstd[m],
                                        gamma[kg + 1], beta[kg + 1]);
                        dst[(size_t)kc * CHU + o] = pack_h2(v0, v1);
                    }
                }
                __syncthreads();
            }
            __threadfence();
            __syncthreads();
            if (tid == 0) {
                if (isW) atomicAdd(&g_wdone, 1);
                else     atomicExch(&g_xready[pb], 1);
            }
            continue;
        }

        // ================= GEMM UNIT =================
        const int v = u - NU_PREP;
        const int tb = v >> 3, ep = v & 7, et0 = ep * 2;

        if (tid == 0) {
            if (!wok) { while (atomicAdd(&g_wdone, 0) < NU_W) __nanosleep(200); wok = true; }
            while (atomicAdd(&g_xready[tb], 0) == 0) __nanosleep(200);
            __threadfence();
        }
        __syncthreads();

        for (int i = tid; i < 1024; i += 256) s_su[i] = 0.f;
        __syncthreads();

        const uint32_t* Ab = g_xnt + (size_t)tb * NKC * CHU;

        auto stage_load = [&](uint32_t cc, int i) {
            int st = cc % 3;
            MBARRIER_WAIT_RELAXED(mb_free + 8 * st, ((cc / 3) + 1) & 1);
            int et = et0 + (i >> 4), k2 = i & 15;
            const uint32_t* As = Ab + (size_t)(k2 * 2) * CHU;
            const uint32_t* Bs = g_wpt + ((size_t)et * NKC + k2 * 2) * CHU;
            uint32_t d = sb + st * (STAGE_U32 * 4);
#pragma unroll
            for (int q = 0; q < 4; q++) {
                int id = q * 256 + tid;
                CP_ASYNC16(d + id * 16, As + id * 4);
                CP_ASYNC16(d + 16384 + id * 16, Bs + id * 4);
            }
            CPA_MBAR_ARRIVE(mb_full + 8 * st);
        };
        stage_load(rc, 0); stage_load(rc + 1, 1);

        float acc[4][4][4];
#pragma unroll
        for (int mf = 0; mf < 4; mf++)
#pragma unroll
            for (int nf = 0; nf < 4; nf++)
#pragma unroll
                for (int r = 0; r < 4; r++) acc[mf][nf][r] = 0.f;

        for (int i = 0; i < 32; i++) {
            if (i + 2 < 32) stage_load(rc + i + 2, i + 2);

            const uint32_t cc = rc + i;
            const int st = cc % 3;
            MBARRIER_WAIT(mb_full + 8 * st, (cc / 3) & 1);

            const uint32_t* St = smu + st * STAGE_U32;
            // B double-buffer across ksg
            uint4 bq[2][2];
            bq[0][0] = *reinterpret_cast<const uint4*>(St + boff);
            bq[0][1] = *reinterpret_cast<const uint4*>(St + boff + 256);
#pragma unroll
            for (int ksg = 0; ksg < 4; ksg++) {
                const int cur = ksg & 1, nxt = cur ^ 1;
                if (ksg < 3) {
                    const int ko = ((ksg + 1) >> 1) * 2048 + ((ksg + 1) & 1) * 128;
                    bq[nxt][0] = *reinterpret_cast<const uint4*>(St + boff + ko);
                    bq[nxt][1] = *reinterpret_cast<const uint4*>(St + boff + ko + 256);
                }
                const int ksub = ksg >> 1, ks = ksg & 1;
                const uint32_t* As = St + ksub * 2048 + aoff + ks * 128;
                uint32_t a[4][4];
#pragma unroll
                for (int mf = 0; mf < 4; mf++) {
                    uint4 vv = *reinterpret_cast<const uint4*>(As + mf * 256);
                    a[mf][0] = vv.x; a[mf][1] = vv.y; a[mf][2] = vv.z; a[mf][3] = vv.w;
                }
#pragma unroll
                for (int mf = 0; mf < 4; mf++) {
                    mma_f16(acc[mf][0], a[mf], bq[cur][0].x, bq[cur][0].y);
                    mma_f16(acc[mf][1], a[mf], bq[cur][0].z, bq[cur][0].w);
                    mma_f16(acc[mf][2], a[mf], bq[cur][1].x, bq[cur][1].y);
                    mma_f16(acc[mf][3], a[mf], bq[cur][1].z, bq[cur][1].w);
                }
            }
            // warp-level consume arrive (free barrier count = 8)
            __syncwarp();
            if (lane == 0) MBAR_ARRIVE(mb_free + 8 * st);

            if ((i & 15) == 15) {
                const int et = et0 + (i >> 4);
#pragma unroll
                for (int mf = 0; mf < 4; mf++) {
                    float pr0[8], pr1[8];
#pragma unroll
                    for (int n = 0; n < 8; n++) { pr0[n] = 0.f; pr1[n] = 0.f; }
#pragma unroll
                    for (int nf = 0; nf < 4; nf++) {
                        int col0 = et * 128 + wn * 32 + nf * 8 + 2 * t;
                        float bp0 = bp[col0], bp1 = bp[col0 + 1];
                        float s00 = silu_f(acc[mf][nf][0] + bp0);
                        float s01 = silu_f(acc[mf][nf][1] + bp1);
                        float s10 = silu_f(acc[mf][nf][2] + bp0);
                        float s11 = silu_f(acc[mf][nf][3] + bp1);
                        const float* wrow = g_wst + col0 * 8;
                        float4 wa0 = *reinterpret_cast<const float4*>(wrow);
                        float4 wa1 = *reinterpret_cast<const float4*>(wrow + 4);
                        float4 wb0 = *reinterpret_cast<const float4*>(wrow + 8);
                        float4 wb1 = *reinterpret_cast<const float4*>(wrow + 12);
                        float wa[8] = {wa0.x, wa0.y, wa0.z, wa0.w, wa1.x, wa1.y, wa1.z, wa1.w};
                        float wb[8] = {wb0.x, wb0.y, wb0.z, wb0.w, wb1.x, wb1.y, wb1.z, wb1.w};
#pragma unroll
                        for (int n = 0; n < 8; n++) {
                            pr0[n] = fmaf(s00, wa[n], fmaf(s01, wb[n], pr0[n]));
                            pr1[n] = fmaf(s10, wa[n], fmaf(s11, wb[n], pr1[n]));
                        }
                    }
#pragma unroll
                    for (int n = 0; n < 8; n++) {
                        pr0[n] += __shfl_xor_sync(0xFFFFFFFFu, pr0[n], 1);
                        pr0[n] += __shfl_xor_sync(0xFFFFFFFFu, pr0[n], 2);
                        pr1[n] += __shfl_xor_sync(0xFFFFFFFFu, pr1[n], 1);
                        pr1[n] += __shfl_xor_sync(0xFFFFFFFFu, pr1[n], 2);
                    }
                    if (t == 0) {
                        int r0 = wm * 64 + mf * 16 + g;
#pragma unroll
                        for (int n = 0; n < 8; n++) {
                            atomicAdd(&s_su[r0 * 8 + n], pr0[n]);
                            atomicAdd(&s_su[(r0 + 8) * 8 + n], pr1[n]);
                        }
                    }
                }
#pragma unroll
                for (int mf = 0; mf < 4; mf++)
#pragma unroll
                    for (int nf = 0; nf < 4; nf++)
#pragma unroll
                        for (int r = 0; r < 4; r++) acc[mf][nf][r] = 0.f;
            }
        }
        rc += 32;

        // flush su, bump done, last finisher does phase2 + tail
        __syncthreads();
        float* gsu = g_su + (size_t)tb * 1024;
        for (int i = tid; i < 1024; i += 256) atomicAdd(&gsu[i], s_su[i]);
        __threadfence();
        __syncthreads();
        if (tid == 0) s_bc[1] = atomicAdd(&g_done[tb], 1);
        __syncthreads();
        if (s_bc[1] == 7) {
            __threadfence();
            for (int i = tid; i < 1024; i += 256) {
                int n = i & 7;
                s_su[i] = silu_f(gsu[i] + bst[n] + istate[n]);
            }
            __syncthreads();
            const float4* x4 = reinterpret_cast<const float4*>(x + (size_t)tb * 128 * DD);
            float4*       o4 = reinterpret_cast<float4*>(out + (size_t)tb * 128 * DD);
            for (int idx = tid; idx < 128 * (DD / 4); idx += 256) {
                int tt2 = idx >> 8, cc2 = idx & 255;
                float4 xv  = x4[idx];
                float4 cs0 = *reinterpret_cast<const float4*>(s_su + tt2 * NS);
                float4 cs1 = *reinterpret_cast<const float4*>(s_su + tt2 * NS + 4);
                float xin[4] = {xv.x, xv.y, xv.z, xv.w};
                float ov[4];
                int d0 = cc2 * 4;
#pragma unroll
                for (int dd = 0; dd < 4; dd++) {
                    int d = d0 + dd;
                    const float4* wo = reinterpret_cast<const float4*>(Wo + (size_t)d * NS);
                    float4 w0 = wo[0], w1 = wo[1];
                    float o = bo[d];
                    o = fmaf(cs0.x, w0.x, o); o = fmaf(cs0.y, w0.y, o);
                    o = fmaf(cs0.z, w0.z, o); o = fmaf(cs0.w, w0.w, o);
                    o = fmaf(cs1.x, w1.x, o); o = fmaf(cs1.y, w1.y, o);
                    o = fmaf(cs1.z, w1.z, o); o = fmaf(cs1.w, w1.w, o);
                    ov[dd] = xin[dd] + o;
                }
                o4[idx] = make_float4(ov[0], ov[1], ov[2], ov[3]);
            }
        }
    }
}

extern "C" void kernel_launch(void* const* d_in, const int* in_sizes, int n_in,
                              void* d_out, int out_size) {
    (void)in_sizes; (void)n_in; (void)out_size;
    const float* x      = (const float*)d_in[0];
    const float* Wp     = (const float*)d_in[1];
    const float* bp     = (const float*)d_in[2];
    const float* Wst    = (const float*)d_in[3];
    const float* bst    = (const float*)d_in[4];
    const float* Wo     = (const float*)d_in[5];
    const float* bo     = (const float*)d_in[6];
    const float* istate = (const float*)d_in[7];
    const float* gamma  = (const float*)d_in[8];
    const float* beta   = (const float*)d_in[9];

    zerok<<<NBLK, 1024>>>();

    cudaFuncSetAttribute(mamba_pers,
                         cudaFuncAttributeMaxDynamicSharedMemorySize, SMEM_BYTES);
    mamba_pers<<<GRID_P, 256, SMEM_BYTES>>>(x, Wp, gamma, beta, Wst,
                                            bp, bst, Wo, bo, istate, (float*)d_out);
}

// round 17
// speedup vs baseline: 1.0057x; 1.0057x over previous
#include <cuda_runtime.h>
#include <cuda_fp16.h>
#include <cstdint>

// ---------------- problem constants ----------------
#define TT 50176
#define DD 1024
#define EE 2048
#define NS 8
#define EPS 1e-5f

#define NBLK 392
#define NET 16
#define NKC 32
#define CHU 2048
#define STG 3
#define STAGE_U32 8192
#define SU_BYTE   (STG * STAGE_U32 * 4)
#define MBAR_BYTE (SU_BYTE + 4096)
#define BCAST_BYTE (MBAR_BYTE + 48)
#define SMEM_BYTES (BCAST_BYTE + 16)

// unit space: [0,17) W-pack(16)+Wst(1); [17,409) x-pack; [409,3545) GEMM
#define NU_W 17
#define NU_PREP (NU_W + NBLK)
#define NU_TOT (NU_PREP + NBLK * 8)
#define GRID_P 304

// ---------------- scratch ----------------
__device__ uint32_t g_xnt[(size_t)NBLK * NKC * CHU];
__device__ uint32_t g_wpt[(size_t)NET * NKC * CHU];
__device__ float    g_wst[EE * NS];
__device__ float    g_su[(size_t)NBLK * 1024];
__device__ int      g_unit;
__device__ int      g_done[NBLK];
__device__ int      g_xready[NBLK];
__device__ int      g_wdone;

// ---------------- helpers ----------------
__device__ __forceinline__ float silu_f(float v) { return v * (1.0f / (1.0f + __expf(-v))); }
__device__ __forceinline__ uint32_t smem_u32(const void* p) {
    uint32_t a;
    asm("{ .reg .u64 t; cvta.to.shared.u64 t, %1; cvt.u32.u64 %0, t; }" : "=r"(a) : "l"(p));
    return a;
}
__device__ __forceinline__ uint32_t pack_h2(float lo, float hi) {
    __half2 h = __halves2half2(__float2half_rn(lo), __float2half_rn(hi));
    return *reinterpret_cast<uint32_t*>(&h);
}
#define CP_ASYNC16(dst, src) \
    asm volatile("cp.async.cg.shared.global [%0], [%1], 16;" :: "r"(dst), "l"(src))
#define CPA_MBAR_ARRIVE(addr) \
    asm volatile("cp.async.mbarrier.arrive.noinc.shared.b64 [%0];" :: "r"(addr) : "memory")
#define MBARRIER_INIT(addr, cnt) \
    asm volatile("mbarrier.init.shared.b64 [%0], %1;" :: "r"(addr), "r"(cnt) : "memory")
#define MBAR_ARRIVE(addr) \
    asm volatile("mbarrier.arrive.shared.b64 _, [%0];" :: "r"(addr) : "memory")

#define MBARRIER_WAIT(addr, ph) do {                                            \
    uint32_t _m = (addr), _p = (uint32_t)(ph), _d;                              \
    asm volatile("{ .reg .pred p; mbarrier.try_wait.parity.acquire.cta.shared::cta.b64 p, [%1], %2; selp.b32 %0,1,0,p; }" \
        : "=r"(_d) : "r"(_m), "r"(_p) : "memory");                              \
    if (!_d) { asm volatile(                                                    \
        "{ .reg .pred P; WL%=: mbarrier.try_wait.parity.acquire.cta.shared::cta.b64 P, [%0], %1, 0x989680;" \
        " @P bra.uni WD%=; bra.uni WL%=; WD%=: }" :: "r"(_m), "r"(_p) : "memory"); } \
} while (0)

#define MBARRIER_WAIT_RELAXED(addr, ph) do {                                    \
    uint32_t _m = (addr), _p = (uint32_t)(ph), _d;                              \
    asm volatile("{ .reg .pred p; mbarrier.try_wait.parity.relaxed.cta.shared::cta.b64 p, [%1], %2, 0x989680; selp.b32 %0,1,0,p; }" \
        : "=r"(_d) : "r"(_m), "r"(_p) : "memory");                              \
    if (!_d) { asm volatile(                                                    \
        "{ .reg .pred P; WL%=: mbarrier.try_wait.parity.relaxed.cta.shared::cta.b64 P, [%0], %1, 0x989680;" \
        " @P bra.uni WD%=; bra.uni WL%=; WD%=: }" :: "r"(_m), "r"(_p) : "memory"); } \
} while (0)

__device__ __forceinline__ void mma_f16(float d[4], const uint32_t a[4],
                                        uint32_t b0, uint32_t b1) {
    asm volatile(
        "mma.sync.aligned.m16n8k16.row.col.f32.f16.f16.f32 "
        "{%0,%1,%2,%3}, {%4,%5,%6,%7}, {%8,%9}, {%0,%1,%2,%3};"
        : "+f"(d[0]), "+f"(d[1]), "+f"(d[2]), "+f"(d[3])
        : "r"(a[0]), "r"(a[1]), "r"(a[2]), "r"(a[3]), "r"(b0), "r"(b1));
}

// ---------------- kernel 0: zero scratch + counters ----------------
__global__ void __launch_bounds__(1024)
zerok() {
    const int b = blockIdx.x, tid = threadIdx.x;
    g_su[(size_t)b * 1024 + tid] = 0.f;
    if (tid == 0) {
        g_done[b] = 0;
        g_xready[b] = 0;
        if (b == 0) { g_unit = 0; g_wdone = 0; }
    }
}

// ---- persistent kernel: prep units + GEMM units, one dynamic queue ----
__global__ void __launch_bounds__(256, 2)
mamba_pers(const float* __restrict__ x,   const float* __restrict__ Wp,
           const float* __restrict__ gamma, const float* __restrict__ beta,
           const float* __restrict__ Wst, const float* __restrict__ bp,
           const float* __restrict__ bst, const float* __restrict__ Wo,
           const float* __restrict__ bo,  const float* __restrict__ istate,
           float* __restrict__ out)
{
    extern __shared__ uint32_t smu[];
    float* s_su = reinterpret_cast<float*>(reinterpret_cast<char*>(smu) + SU_BYTE);
    int*  s_bc  = reinterpret_cast<int*>(reinterpret_cast<char*>(smu) + BCAST_BYTE);
    float* s_t    = reinterpret_cast<float*>(smu);          // prep scratch
    float* s_mu   = s_t + 128 * 36;
    float* s_rstd = s_mu + 128;
    const int tid = threadIdx.x, lane = tid & 31, wid = tid >> 5;
    const int wm = wid >> 2, wn = wid & 3;
    const uint32_t sb = smem_u32(smu);
    const uint32_t mb_full = sb + MBAR_BYTE;
    const uint32_t mb_free = sb + MBAR_BYTE + 24;
    const int g = lane >> 2, t = lane & 3;

    if (tid == 0) {
#pragma unroll
        for (int s = 0; s < STG; s++) {
            MBARRIER_INIT(mb_full + 8 * s, 256);
            MBARRIER_INIT(mb_free + 8 * s, 256);
        }
    }
    __syncthreads();

    const int aoff = wm * 1024 + lane * 4;
    const int boff = 4096 + wn * 512 + lane * 4;

    uint32_t rc = 0;
    bool wok = false;

    for (;;) {
        __syncthreads();
        if (tid == 0) s_bc[0] = atomicAdd(&g_unit, 1);
        __syncthreads();
        const int u = s_bc[0];
        if (u >= NU_TOT) break;

        if (u < NU_PREP) {
            // ================= PREP UNIT =================
            if (u == NU_W - 1) {          // Wst transpose
                for (int i = tid; i < EE * NS; i += 256) {
                    int e = i >> 3, n = i & 7;
                    g_wst[i] = Wst[n * EE + e];
                }
                __threadfence();
                __syncthreads();
                if (tid == 0) atomicAdd(&g_wdone, 1);
                continue;
            }
            const bool isW = (u < NU_W - 1);
            const int pb = isW ? u : (u - NU_W);
            const float* src = isW ? Wp + (size_t)pb * 128 * DD
                                   : x + (size_t)pb * 128 * DD;
            uint32_t* dst = isW ? g_wpt + (size_t)pb * NKC * CHU
                                : g_xnt + (size_t)pb * NKC * CHU;

            if (!isW) {
                int tk = tid >> 1, half = tid & 1;
                const float4* xr = reinterpret_cast<const float4*>(
                    src + (size_t)tk * DD + half * (DD / 2));
                float s = 0.f, ss = 0.f;
#pragma unroll 4
                for (int i = 0; i < DD / 8; i++) {
                    float4 v = xr[i];
                    s  += v.x + v.y + v.z + v.w;
                    ss += v.x * v.x + v.y * v.y + v.z * v.z + v.w * v.w;
                }
                s  += __shfl_xor_sync(0xFFFFFFFFu, s, 1);
                ss += __shfl_xor_sync(0xFFFFFFFFu, ss, 1);
                if (!half) {
                    float mu = s * (1.0f / DD);
                    float var = ss * (1.0f / DD) - mu * mu;
                    s_mu[tk] = mu; s_rstd[tk] = rsqrtf(var + EPS);
                }
            }
            __syncthreads();

            for (int kc = 0; kc < NKC; kc++) {
#pragma unroll
                for (int i = 0; i < 4; i++) {
                    int id = i * 256 + tid;
                    int row = id >> 3, c4 = id & 7;
                    float4 v = *reinterpret_cast<const float4*>(
                        src + (size_t)row * DD + kc * 32 + c4 * 4);
                    *reinterpret_cast<float4*>(s_t + row * 36 + c4 * 4) = v;
                }
                __syncthreads();
                if (isW) {
#pragma unroll
                    for (int j = 0; j < 8; j++) {
                        int o = j * 256 + tid;
                        int MS = o >> 7, NFP = MS >> 1, ks = MS & 1;
                        int ln = (o >> 2) & 31, gg = ln >> 2, tt = ln & 3, jj = o & 3;
                        int n  = NFP * 16 + (jj >> 1) * 8 + gg;
                        int k0 = ks * 16 + (jj & 1) * 8 + 2 * tt;
                        float2 sv = *reinterpret_cast<const float2*>(s_t + n * 36 + k0);
                        dst[(size_t)kc * CHU + o] = pack_h2(sv.x, sv.y);
                    }
                } else {
#pragma unroll
                    for (int j = 0; j < 8; j++) {
                        int o = j * 256 + tid;
                        int MS = o >> 7, MF = MS >> 1, ks = MS & 1;
                        int ln = (o >> 2) & 31, gg = ln >> 2, tt = ln & 3, r = o & 3;
                        int m  = MF * 16 + (r & 1) * 8 + gg;
                        int k0 = ks * 16 + (r >> 1) * 8 + 2 * tt;
                        int kg = kc * 32 + k0;
                        float2 sv = *reinterpret_cast<const float2*>(s_t + m * 36 + k0);
                        float2 gv = *reinterpret_cast<const float2*>(gamma + kg);
                        float2 bv = *reinterpret_cast<const float2*>(beta + kg);
                        float mu = s_mu[m], rs = s_rstd[m];
                        dst[(size_t)kc * CHU + o] =
                            pack_h2(fmaf((sv.x - mu) * rs, gv.x, bv.x),
                                    fmaf((sv.y - mu) * rs, gv.y, bv.y));
                    }
                }
                __syncthreads();
            }
            __threadfence();
            __syncthreads();
            if (tid == 0) {
                if (isW) atomicAdd(&g_wdone, 1);
                else     atomicExch(&g_xready[pb], 1);
            }
            continue;
        }

        // ================= GEMM UNIT =================
        const int v = u - NU_PREP;
        const int tb = v >> 3, ep = v & 7, et0 = ep * 2;

        if (tid == 0) {
            if (!wok) { while (atomicAdd(&g_wdone, 0) < NU_W) __nanosleep(200); wok = true; }
            while (atomicAdd(&g_xready[tb], 0) == 0) __nanosleep(200);
            __threadfence();
        }
        __syncthreads();

        for (int i = tid; i < 1024; i += 256) s_su[i] = 0.f;
        __syncthreads();

        const uint32_t* Ab = g_xnt + (size_t)tb * NKC * CHU;

        auto stage_load = [&](uint32_t cc, int i) {
            int st = cc % 3;
            MBARRIER_WAIT_RELAXED(mb_free + 8 * st, ((cc / 3) + 1) & 1);
            int et = et0 + (i >> 4), k2 = i & 15;
            const uint32_t* As = Ab + (size_t)(k2 * 2) * CHU;
            const uint32_t* Bs = g_wpt + ((size_t)et * NKC + k2 * 2) * CHU;
            uint32_t d = sb + st * (STAGE_U32 * 4);
#pragma unroll
            for (int q = 0; q < 4; q++) {
                int id = q * 256 + tid;
                CP_ASYNC16(d + id * 16, As + id * 4);
                CP_ASYNC16(d + 16384 + id * 16, Bs + id * 4);
            }
            CPA_MBAR_ARRIVE(mb_full + 8 * st);
        };
        stage_load(rc, 0); stage_load(rc + 1, 1);

        float acc[4][4][4];
#pragma unroll
        for (int mf = 0; mf < 4; mf++)
#pragma unroll
            for (int nf = 0; nf < 4; nf++)
#pragma unroll
                for (int r = 0; r < 4; r++) acc[mf][nf][r] = 0.f;

        for (int i = 0; i < 32; i++) {
            if (i + 2 < 32) stage_load(rc + i + 2, i + 2);

            const uint32_t cc = rc + i;
            const int st = cc % 3;
            MBARRIER_WAIT(mb_full + 8 * st, (cc / 3) & 1);

            const uint32_t* St = smu + st * STAGE_U32;
#pragma unroll
            for (int ksg = 0; ksg < 4; ksg++) {
                const int ksub = ksg >> 1, ks = ksg & 1;
                const uint32_t* As = St + ksub * 2048 + aoff + ks * 128;
                const uint32_t* Bs = St + ksub * 2048 + boff + ks * 128;
                uint32_t a[4][4], b[2][4];
#pragma unroll
                for (int mf = 0; mf < 4; mf++) {
                    uint4 vv = *reinterpret_cast<const uint4*>(As + mf * 256);
                    a[mf][0] = vv.x; a[mf][1] = vv.y; a[mf][2] = vv.z; a[mf][3] = vv.w;
                }
#pragma unroll
                for (int p = 0; p < 2; p++) {
                    uint4 vv = *reinterpret_cast<const uint4*>(Bs + p * 256);
                    b[p][0] = vv.x; b[p][1] = vv.y; b[p][2] = vv.z; b[p][3] = vv.w;
                }
#pragma unroll
                for (int mf = 0; mf < 4; mf++)
#pragma unroll
                    for (int p = 0; p < 2; p++) {
                        mma_f16(acc[mf][p * 2],     a[mf], b[p][0], b[p][1]);
                        mma_f16(acc[mf][p * 2 + 1], a[mf], b[p][2], b[p][3]);
                    }
            }
            MBAR_ARRIVE(mb_free + 8 * st);

            if ((i & 15) == 15) {
                const int et = et0 + (i >> 4);
#pragma unroll
                for (int mf = 0; mf < 4; mf++) {
                    float pr0[8], pr1[8];
#pragma unroll
                    for (int n = 0; n < 8; n++) { pr0[n] = 0.f; pr1[n] = 0.f; }
#pragma unroll
                    for (int nf = 0; nf < 4; nf++) {
                        int col0 = et * 128 + wn * 32 + nf * 8 + 2 * t;
                        float bp0 = bp[col0], bp1 = bp[col0 + 1];
                        float s00 = silu_f(acc[mf][nf][0] + bp0);
                        float s01 = silu_f(acc[mf][nf][1] + bp1);
                        float s10 = silu_f(acc[mf][nf][2] + bp0);
                        float s11 = silu_f(acc[mf][nf][3] + bp1);
                        const float* wrow = g_wst + col0 * 8;
                        float4 wa0 = *reinterpret_cast<const float4*>(wrow);
                        float4 wa1 = *reinterpret_cast<const float4*>(wrow + 4);
                        float4 wb0 = *reinterpret_cast<const float4*>(wrow + 8);
                        float4 wb1 = *reinterpret_cast<const float4*>(wrow + 12);
                        float wa[8] = {wa0.x, wa0.y, wa0.z, wa0.w, wa1.x, wa1.y, wa1.z, wa1.w};
                        float wb[8] = {wb0.x, wb0.y, wb0.z, wb0.w, wb1.x, wb1.y, wb1.z, wb1.w};
#pragma unroll
                        for (int n = 0; n < 8; n++) {
                            pr0[n] = fmaf(s00, wa[n], fmaf(s01, wb[n], pr0[n]));
                            pr1[n] = fmaf(s10, wa[n], fmaf(s11, wb[n], pr1[n]));
                        }
                    }
#pragma unroll
                    for (int n = 0; n < 8; n++) {
                        pr0[n] += __shfl_xor_sync(0xFFFFFFFFu, pr0[n], 1);
                        pr0[n] += __shfl_xor_sync(0xFFFFFFFFu, pr0[n], 2);
                        pr1[n] += __shfl_xor_sync(0xFFFFFFFFu, pr1[n], 1);
                        pr1[n] += __shfl_xor_sync(0xFFFFFFFFu, pr1[n], 2);
                    }
                    if (t == 0) {
                        int r0 = wm * 64 + mf * 16 + g;
#pragma unroll
                        for (int n = 0; n < 8; n++) {
                            atomicAdd(&s_su[r0 * 8 + n], pr0[n]);
                            atomicAdd(&s_su[(r0 + 8) * 8 + n], pr1[n]);
                        }
                    }
                }
#pragma unroll
                for (int mf = 0; mf < 4; mf++)
#pragma unroll
                    for (int nf = 0; nf < 4; nf++)
#pragma unroll
                        for (int r = 0; r < 4; r++) acc[mf][nf][r] = 0.f;
            }
        }
        rc += 32;

        // flush su, bump done, last finisher does phase2 + tail
        __syncthreads();
        float* gsu = g_su + (size_t)tb * 1024;
        for (int i = tid; i < 1024; i += 256) atomicAdd(&gsu[i], s_su[i]);
        __threadfence();
        __syncthreads();
        if (tid == 0) s_bc[1] = atomicAdd(&g_done[tb], 1);
        __syncthreads();
        if (s_bc[1] == 7) {
            __threadfence();
            for (int i = tid; i < 1024; i += 256) {
                int n = i & 7;
                s_su[i] = silu_f(gsu[i] + bst[n] + istate[n]);
            }
            __syncthreads();
            const float4* x4 = reinterpret_cast<const float4*>(x + (size_t)tb * 128 * DD);
            float4*       o4 = reinterpret_cast<float4*>(out + (size_t)tb * 128 * DD);
            for (int idx = tid; idx < 128 * (DD / 4); idx += 256) {
                int tt2 = idx >> 8, cc2 = idx & 255;
                float4 xv  = x4[idx];
                float4 cs0 = *reinterpret_cast<const float4*>(s_su + tt2 * NS);
                float4 cs1 = *reinterpret_cast<const float4*>(s_su + tt2 * NS + 4);
                float xin[4] = {xv.x, xv.y, xv.z, xv.w};
                float ov[4];
                int d0 = cc2 * 4;
#pragma unroll
                for (int dd = 0; dd < 4; dd++) {
                    int d = d0 + dd;
                    const float4* wo = reinterpret_cast<const float4*>(Wo + (size_t)d * NS);
                    float4 w0 = wo[0], w1 = wo[1];
                    float o = bo[d];
                    o = fmaf(cs0.x, w0.x, o); o = fmaf(cs0.y, w0.y, o);
                    o = fmaf(cs0.z, w0.z, o); o = fmaf(cs0.w, w0.w, o);
                    o = fmaf(cs1.x, w1.x, o); o = fmaf(cs1.y, w1.y, o);
                    o = fmaf(cs1.z, w1.z, o); o = fmaf(cs1.w, w1.w, o);
                    ov[dd] = xin[dd] + o;
                }
                o4[idx] = make_float4(ov[0], ov[1], ov[2], ov[3]);
            }
        }
    }
}

extern "C" void kernel_launch(void* const* d_in, const int* in_sizes, int n_in,
                              void* d_out, int out_size) {
    (void)in_sizes; (void)n_in; (void)out_size;
    const float* x      = (const float*)d_in[0];
    const float* Wp     = (const float*)d_in[1];
    const float* bp     = (const float*)d_in[2];
    const float* Wst    = (const float*)d_in[3];
    const float* bst    = (const float*)d_in[4];
    const float* Wo     = (const float*)d_in[5];
    const float* bo     = (const float*)d_in[6];
    const float* istate = (const float*)d_in[7];
    const float* gamma  = (const float*)d_in[8];
    const float* beta   = (const float*)d_in[9];

    zerok<<<NBLK, 1024>>>();

    cudaFuncSetAttribute(mamba_pers,
                         cudaFuncAttributeMaxDynamicSharedMemorySize, SMEM_BYTES);
    mamba_pers<<<GRID_P, 256, SMEM_BYTES>>>(x, Wp, gamma, beta, Wst,
                                            bp, bst, Wo, bo, istate, (float*)d_out);
}